// round 1
// baseline (speedup 1.0000x reference)
#include <cuda_runtime.h>
#include <cstdint>

#define NN 50000
#define EE 800000

// ---------------- scratch (device globals: no allocation allowed) ----------
__device__ float g_q[NN * 64];
__device__ float g_k[NN * 64];
__device__ float g_v[NN * 64];
__device__ float g_h[NN * 64];    // layer1 skip, then layer1 output (post-relu)
__device__ float g_s2[NN * 64];   // layer2 skip
__device__ float g_alpha[(size_t)EE * 4];
__device__ int g_deg[NN];
__device__ int g_off[NN + 1];
__device__ int g_cur[NN];
__device__ int g_srcs[EE];

// ---------------- f32x2 helpers (sm_100+ packed fp32) -----------------------
__device__ __forceinline__ unsigned long long pack2(float x, float y) {
    unsigned long long r;
    asm("mov.b64 %0, {%1, %2};" : "=l"(r) : "f"(x), "f"(y));
    return r;
}
__device__ __forceinline__ float2 unpack2(unsigned long long v) {
    float2 r;
    asm("mov.b64 {%0, %1}, %2;" : "=f"(r.x), "=f"(r.y) : "l"(v));
    return r;
}
__device__ __forceinline__ unsigned long long ffma2(unsigned long long a,
                                                    unsigned long long b,
                                                    unsigned long long c) {
    unsigned long long d;
    asm("fma.rn.f32x2 %0, %1, %2, %3;" : "=l"(d) : "l"(a), "l"(b), "l"(c));
    return d;
}

// ---------------- CSR build --------------------------------------------------
__global__ void clear_deg_kernel() {
    int i = blockIdx.x * blockDim.x + threadIdx.x;
    if (i < NN) g_deg[i] = 0;
}

__global__ void hist_kernel(const int* __restrict__ ei) {
    int e = blockIdx.x * blockDim.x + threadIdx.x;
    if (e < EE) atomicAdd(&g_deg[ei[EE + e]], 1);
}

__global__ void scan_kernel() {
    __shared__ int sh[1024];
    const int tid = threadIdx.x;
    const int CHUNK = (NN + 1023) / 1024;   // 49
    const int s0 = tid * CHUNK;
    int sum = 0;
    #pragma unroll 4
    for (int i = 0; i < CHUNK; i++) {
        int idx = s0 + i;
        if (idx < NN) sum += g_deg[idx];
    }
    sh[tid] = sum;
    __syncthreads();
    int val = sum;
    for (int off = 1; off < 1024; off <<= 1) {
        int t = (tid >= off) ? sh[tid - off] : 0;
        __syncthreads();
        val += t;
        sh[tid] = val;
        __syncthreads();
    }
    int run = val - sum;   // exclusive prefix
    for (int i = 0; i < CHUNK; i++) {
        int idx = s0 + i;
        if (idx < NN) {
            g_off[idx] = run;
            g_cur[idx] = run;
            run += g_deg[idx];
        }
    }
    if (tid == 0) g_off[NN] = EE;
}

__global__ void scatter_kernel(const int* __restrict__ ei) {
    int e = blockIdx.x * blockDim.x + threadIdx.x;
    if (e < EE) {
        int d = ei[EE + e];
        int p = atomicAdd(&g_cur[d], 1);
        g_srcs[p] = ei[e];
    }
}

// ---------------- fused QKVS GEMM -------------------------------------------
// Computes O_m = X @ W_m^T + b_m for m in {q,k,v,skip}.  BM=128, BN=64 (full
// matrix), BK=32, 128 threads, 8x8 per thread, f32x2 accumulators.
struct G4w {
    const float* W[4];
    const float* b[4];
};

template <int C, int LAYER>
__global__ __launch_bounds__(128) void gemm4_kernel(const float* __restrict__ Xin, G4w a) {
    __shared__ __align__(16) float Xs[32][132];
    __shared__ __align__(16) float Ws[32][68];

    const float* X = (LAYER == 1) ? Xin : g_h;
    const int mat = blockIdx.y;
    const float* W = a.W[mat];
    float* O = (mat == 0) ? g_q : (mat == 1) ? g_k : (mat == 2) ? g_v
               : ((LAYER == 1) ? g_h : g_s2);

    const int row0 = blockIdx.x * 128;
    const int tid = threadIdx.x;
    const int tx = tid & 7;    // 8 cols group (TN=8)
    const int ty = tid >> 3;   // 16 row groups (TM=8)

    unsigned long long acc[8][4];
    #pragma unroll
    for (int i = 0; i < 8; i++)
        #pragma unroll
        for (int j = 0; j < 4; j++) acc[i][j] = 0ull;

    for (int k0 = 0; k0 < C; k0 += 32) {
        // X tile: 128 rows x 32 k (transposed into smem)
        #pragma unroll
        for (int t = 0; t < 8; t++) {
            int idx = tid + t * 128;       // 0..1023
            int r = idx >> 3;
            int kq = idx & 7;
            float4 xv = make_float4(0.f, 0.f, 0.f, 0.f);
            int rg = row0 + r;
            if (rg < NN)
                xv = *reinterpret_cast<const float4*>(X + (size_t)rg * C + k0 + kq * 4);
            Xs[kq * 4 + 0][r] = xv.x;
            Xs[kq * 4 + 1][r] = xv.y;
            Xs[kq * 4 + 2][r] = xv.z;
            Xs[kq * 4 + 3][r] = xv.w;
        }
        // W tile: 64 rows(m) x 32 k (transposed)
        #pragma unroll
        for (int t = 0; t < 4; t++) {
            int idx = tid + t * 128;       // 0..511
            int m = idx >> 3;
            int kq = idx & 7;
            float4 wv = *reinterpret_cast<const float4*>(W + (size_t)m * C + k0 + kq * 4);
            Ws[kq * 4 + 0][m] = wv.x;
            Ws[kq * 4 + 1][m] = wv.y;
            Ws[kq * 4 + 2][m] = wv.z;
            Ws[kq * 4 + 3][m] = wv.w;
        }
        __syncthreads();

        #pragma unroll
        for (int k = 0; k < 32; k++) {
            float4 a0 = *reinterpret_cast<const float4*>(&Xs[k][ty * 8]);
            float4 a1 = *reinterpret_cast<const float4*>(&Xs[k][ty * 8 + 4]);
            const unsigned long long* bp =
                reinterpret_cast<const unsigned long long*>(&Ws[k][tx * 8]);
            unsigned long long b0 = bp[0], b1 = bp[1], b2 = bp[2], b3 = bp[3];
            float av[8] = {a0.x, a0.y, a0.z, a0.w, a1.x, a1.y, a1.z, a1.w};
            #pragma unroll
            for (int i = 0; i < 8; i++) {
                unsigned long long aa = pack2(av[i], av[i]);
                acc[i][0] = ffma2(aa, b0, acc[i][0]);
                acc[i][1] = ffma2(aa, b1, acc[i][1]);
                acc[i][2] = ffma2(aa, b2, acc[i][2]);
                acc[i][3] = ffma2(aa, b3, acc[i][3]);
            }
        }
        __syncthreads();
    }

    const float* bias = a.b[mat];
    float4 bv0 = *reinterpret_cast<const float4*>(bias + tx * 8);
    float4 bv1 = *reinterpret_cast<const float4*>(bias + tx * 8 + 4);
    #pragma unroll
    for (int i = 0; i < 8; i++) {
        int rg = row0 + ty * 8 + i;
        if (rg >= NN) continue;
        float2 c0 = unpack2(acc[i][0]);
        float2 c1 = unpack2(acc[i][1]);
        float2 c2 = unpack2(acc[i][2]);
        float2 c3 = unpack2(acc[i][3]);
        float4 o0 = make_float4(c0.x + bv0.x, c0.y + bv0.y, c1.x + bv0.z, c1.y + bv0.w);
        float4 o1 = make_float4(c2.x + bv1.x, c2.y + bv1.y, c3.x + bv1.z, c3.y + bv1.w);
        *reinterpret_cast<float4*>(O + (size_t)rg * 64 + tx * 8) = o0;
        *reinterpret_cast<float4*>(O + (size_t)rg * 64 + tx * 8 + 4) = o1;
    }
}

// ---------------- per-destination-node attention (warp per node) ------------
// H heads over 64 total dims; GROUP = 32/H lanes per head, 2 dims per lane.
template <int H, bool RELU, bool L1>
__global__ void node_attn_kernel(float* __restrict__ out_param) {
    constexpr int GROUP = 32 / H;
    constexpr int D = 64 / H;
    const float scale = rsqrtf((float)D);

    int warp = (blockIdx.x * blockDim.x + threadIdx.x) >> 5;
    if (warp >= NN) return;
    const int lane = threadIdx.x & 31;
    const int hg = lane / GROUP;

    const float* q = g_q;
    const float* k = g_k;
    const float* v = g_v;
    const float* skip = L1 ? g_h : g_s2;
    float* out = L1 ? g_h : out_param;

    const int beg = g_off[warp];
    const int end = g_off[warp + 1];

    float2 qr = *reinterpret_cast<const float2*>(q + (size_t)warp * 64 + lane * 2);
    const float qx = qr.x * scale, qy = qr.y * scale;

    // pass 1: logits + per-head max
    float m = -1e30f;
    for (int i = beg; i < end; i++) {
        int s = g_srcs[i];
        float2 kk = *reinterpret_cast<const float2*>(k + (size_t)s * 64 + lane * 2);
        float p = qx * kk.x + qy * kk.y;
        #pragma unroll
        for (int o = 1; o < GROUP; o <<= 1) p += __shfl_xor_sync(0xffffffffu, p, o);
        if ((lane & (GROUP - 1)) == 0) g_alpha[(size_t)i * H + hg] = p;
        m = fmaxf(m, p);
    }
    __syncwarp();

    // pass 2: denominator
    float den = 0.f;
    for (int i = beg; i < end; i++)
        den += __expf(g_alpha[(size_t)i * H + hg] - m);
    const float rden = 1.0f / den;

    // pass 3: weighted aggregation of v
    float ax = 0.f, ay = 0.f;
    for (int i = beg; i < end; i++) {
        int s = g_srcs[i];
        float w = __expf(g_alpha[(size_t)i * H + hg] - m) * rden;
        float2 vv = *reinterpret_cast<const float2*>(v + (size_t)s * 64 + lane * 2);
        ax += w * vv.x;
        ay += w * vv.y;
    }

    float2 sk = *reinterpret_cast<const float2*>(skip + (size_t)warp * 64 + lane * 2);
    float ox = ax + sk.x, oy = ay + sk.y;
    if (RELU) {
        ox = fmaxf(ox, 0.f);
        oy = fmaxf(oy, 0.f);
    }
    float2 res = make_float2(ox, oy);
    *reinterpret_cast<float2*>(out + (size_t)warp * 64 + lane * 2) = res;
}

// ---------------- launch ------------------------------------------------------
extern "C" void kernel_launch(void* const* d_in, const int* in_sizes, int n_in,
                              void* d_out, int out_size) {
    (void)in_sizes; (void)n_in; (void)out_size;
    const float* x = (const float*)d_in[0];
    const int* ei = (const int*)d_in[1];

    // CSR by destination (shared by both layers)
    clear_deg_kernel<<<(NN + 255) / 256, 256>>>();
    hist_kernel<<<EE / 256, 256>>>(ei);
    scan_kernel<<<1, 1024>>>();
    scatter_kernel<<<EE / 256, 256>>>(ei);

    const dim3 ggrid((NN + 127) / 128, 4);

    // layer 1
    G4w w1;
    w1.W[0] = (const float*)d_in[2];  w1.b[0] = (const float*)d_in[3];   // Wq1
    w1.W[1] = (const float*)d_in[4];  w1.b[1] = (const float*)d_in[5];   // Wk1
    w1.W[2] = (const float*)d_in[6];  w1.b[2] = (const float*)d_in[7];   // Wv1
    w1.W[3] = (const float*)d_in[8];  w1.b[3] = (const float*)d_in[9];   // Ws1
    gemm4_kernel<128, 1><<<ggrid, 128>>>(x, w1);
    node_attn_kernel<4, true, true><<<(NN * 32) / 256, 256>>>(nullptr);

    // layer 2
    G4w w2;
    w2.W[0] = (const float*)d_in[10]; w2.b[0] = (const float*)d_in[11];  // Wq2
    w2.W[1] = (const float*)d_in[12]; w2.b[1] = (const float*)d_in[13];  // Wk2
    w2.W[2] = (const float*)d_in[14]; w2.b[2] = (const float*)d_in[15];  // Wv2
    w2.W[3] = (const float*)d_in[16]; w2.b[3] = (const float*)d_in[17];  // Ws2
    gemm4_kernel<64, 2><<<ggrid, 128>>>(x, w2);
    node_attn_kernel<1, false, false><<<(NN * 32) / 256, 256>>>((float*)d_out);
}

// round 2
// speedup vs baseline: 1.1403x; 1.1403x over previous
#include <cuda_runtime.h>
#include <cstdint>

#define NN 50000
#define EE 800000

// ---------------- scratch (device globals: no allocation allowed) ----------
__device__ float g_q[NN * 64];
__device__ float g_k[NN * 64];
__device__ float g_v[NN * 64];
__device__ float g_h[NN * 64];    // layer1 skip, then layer1 output (post-relu)
__device__ float g_s2[NN * 64];   // layer2 skip
__device__ int g_deg[NN];
__device__ int g_off[NN + 1];
__device__ int g_cur[NN];
__device__ int g_srcs[EE];

// ---------------- f32x2 helpers (sm_100+ packed fp32) -----------------------
__device__ __forceinline__ unsigned long long pack2(float x, float y) {
    unsigned long long r;
    asm("mov.b64 %0, {%1, %2};" : "=l"(r) : "f"(x), "f"(y));
    return r;
}
__device__ __forceinline__ float2 unpack2(unsigned long long v) {
    float2 r;
    asm("mov.b64 {%0, %1}, %2;" : "=f"(r.x), "=f"(r.y) : "l"(v));
    return r;
}
__device__ __forceinline__ unsigned long long ffma2(unsigned long long a,
                                                    unsigned long long b,
                                                    unsigned long long c) {
    unsigned long long d;
    asm("fma.rn.f32x2 %0, %1, %2, %3;" : "=l"(d) : "l"(a), "l"(b), "l"(c));
    return d;
}

// ---------------- CSR build --------------------------------------------------
__global__ void hist_kernel(const int* __restrict__ ei) {
    int e = blockIdx.x * blockDim.x + threadIdx.x;
    if (e < EE) atomicAdd(&g_deg[__ldg(ei + EE + e)], 1);
}

__global__ void scan_kernel() {
    __shared__ int sh[1024];
    const int tid = threadIdx.x;
    const int CHUNK = (NN + 1023) / 1024;   // 49
    const int s0 = tid * CHUNK;
    int sum = 0;
    #pragma unroll 4
    for (int i = 0; i < CHUNK; i++) {
        int idx = s0 + i;
        if (idx < NN) sum += g_deg[idx];
    }
    sh[tid] = sum;
    __syncthreads();
    int val = sum;
    for (int off = 1; off < 1024; off <<= 1) {
        int t = (tid >= off) ? sh[tid - off] : 0;
        __syncthreads();
        val += t;
        sh[tid] = val;
        __syncthreads();
    }
    int run = val - sum;   // exclusive prefix
    for (int i = 0; i < CHUNK; i++) {
        int idx = s0 + i;
        if (idx < NN) {
            g_off[idx] = run;
            g_cur[idx] = run;
            run += g_deg[idx];
        }
    }
    if (tid == 0) g_off[NN] = EE;
}

__global__ void scatter_kernel(const int* __restrict__ ei) {
    int e = blockIdx.x * blockDim.x + threadIdx.x;
    if (e < EE) {
        int d = __ldg(ei + EE + e);
        int p = atomicAdd(&g_cur[d], 1);
        g_srcs[p] = __ldg(ei + e);
    }
}

// ---------------- fused QKVS GEMM -------------------------------------------
// Computes O_m = (X @ W_m^T + b_m) * scale_m.  BM=128, BN=64 (full matrix),
// BK=32, 128 threads, 8x8 per thread, f32x2 accumulators.
// mat 0 (=q) gets scale = 1/sqrt(D) folded in; others scale=1.
struct G4w {
    const float* W[4];
    const float* b[4];
};

template <int C, int LAYER>
__global__ __launch_bounds__(128) void gemm4_kernel(const float* __restrict__ Xin, G4w a,
                                                    float qscale) {
    __shared__ __align__(16) float Xs[32][132];
    __shared__ __align__(16) float Ws[32][68];

    const float* X = (LAYER == 1) ? Xin : g_h;
    const int mat = blockIdx.y;
    const float* W = a.W[mat];
    float* O = (mat == 0) ? g_q : (mat == 1) ? g_k : (mat == 2) ? g_v
               : ((LAYER == 1) ? g_h : g_s2);
    const float scale = (mat == 0) ? qscale : 1.0f;

    const int row0 = blockIdx.x * 128;
    const int tid = threadIdx.x;
    const int tx = tid & 7;    // 8 cols group (TN=8)
    const int ty = tid >> 3;   // 16 row groups (TM=8)

    unsigned long long acc[8][4];
    #pragma unroll
    for (int i = 0; i < 8; i++)
        #pragma unroll
        for (int j = 0; j < 4; j++) acc[i][j] = 0ull;

    for (int k0 = 0; k0 < C; k0 += 32) {
        // X tile: 128 rows x 32 k (transposed into smem)
        #pragma unroll
        for (int t = 0; t < 8; t++) {
            int idx = tid + t * 128;       // 0..1023
            int r = idx >> 3;
            int kq = idx & 7;
            float4 xv = make_float4(0.f, 0.f, 0.f, 0.f);
            int rg = row0 + r;
            if (rg < NN)
                xv = *reinterpret_cast<const float4*>(X + (size_t)rg * C + k0 + kq * 4);
            Xs[kq * 4 + 0][r] = xv.x;
            Xs[kq * 4 + 1][r] = xv.y;
            Xs[kq * 4 + 2][r] = xv.z;
            Xs[kq * 4 + 3][r] = xv.w;
        }
        // W tile: 64 rows(m) x 32 k (transposed)
        #pragma unroll
        for (int t = 0; t < 4; t++) {
            int idx = tid + t * 128;       // 0..511
            int m = idx >> 3;
            int kq = idx & 7;
            float4 wv = *reinterpret_cast<const float4*>(W + (size_t)m * C + k0 + kq * 4);
            Ws[kq * 4 + 0][m] = wv.x;
            Ws[kq * 4 + 1][m] = wv.y;
            Ws[kq * 4 + 2][m] = wv.z;
            Ws[kq * 4 + 3][m] = wv.w;
        }
        __syncthreads();

        #pragma unroll
        for (int k = 0; k < 32; k++) {
            float4 a0 = *reinterpret_cast<const float4*>(&Xs[k][ty * 8]);
            float4 a1 = *reinterpret_cast<const float4*>(&Xs[k][ty * 8 + 4]);
            const unsigned long long* bp =
                reinterpret_cast<const unsigned long long*>(&Ws[k][tx * 8]);
            unsigned long long b0 = bp[0], b1 = bp[1], b2 = bp[2], b3 = bp[3];
            float av[8] = {a0.x, a0.y, a0.z, a0.w, a1.x, a1.y, a1.z, a1.w};
            #pragma unroll
            for (int i = 0; i < 8; i++) {
                unsigned long long aa = pack2(av[i], av[i]);
                acc[i][0] = ffma2(aa, b0, acc[i][0]);
                acc[i][1] = ffma2(aa, b1, acc[i][1]);
                acc[i][2] = ffma2(aa, b2, acc[i][2]);
                acc[i][3] = ffma2(aa, b3, acc[i][3]);
            }
        }
        __syncthreads();
    }

    const float* bias = a.b[mat];
    float4 bv0 = *reinterpret_cast<const float4*>(bias + tx * 8);
    float4 bv1 = *reinterpret_cast<const float4*>(bias + tx * 8 + 4);
    #pragma unroll
    for (int i = 0; i < 8; i++) {
        int rg = row0 + ty * 8 + i;
        if (rg >= NN) continue;
        float2 c0 = unpack2(acc[i][0]);
        float2 c1 = unpack2(acc[i][1]);
        float2 c2 = unpack2(acc[i][2]);
        float2 c3 = unpack2(acc[i][3]);
        float4 o0 = make_float4((c0.x + bv0.x) * scale, (c0.y + bv0.y) * scale,
                                (c1.x + bv0.z) * scale, (c1.y + bv0.w) * scale);
        float4 o1 = make_float4((c2.x + bv1.x) * scale, (c2.y + bv1.y) * scale,
                                (c3.x + bv1.z) * scale, (c3.y + bv1.w) * scale);
        *reinterpret_cast<float4*>(O + (size_t)rg * 64 + tx * 8) = o0;
        *reinterpret_cast<float4*>(O + (size_t)rg * 64 + tx * 8 + 4) = o1;
    }
}

// ---------------- per-destination-node attention (warp per node) ------------
// Single-pass online softmax (flash-attention style).
// H heads over 64 total dims; GROUP = 32/H lanes per head, 2 dims per lane.
// q is pre-scaled by 1/sqrt(D) in the GEMM epilogue.
template <int H, bool RELU, bool L1>
__global__ void node_attn_kernel(float* __restrict__ out_param) {
    constexpr int GROUP = 32 / H;

    int warp = (blockIdx.x * blockDim.x + threadIdx.x) >> 5;
    if (warp >= NN) return;
    const int lane = threadIdx.x & 31;

    const float* skip = L1 ? g_h : g_s2;
    float* out = L1 ? g_h : out_param;

    const int beg = g_off[warp];
    const int end = g_off[warp + 1];

    float2 qr = *reinterpret_cast<const float2*>(g_q + (size_t)warp * 64 + lane * 2);
    const float qx = qr.x, qy = qr.y;

    float m = -1e30f;
    float den = 0.f, ax = 0.f, ay = 0.f;

    #pragma unroll 2
    for (int i = beg; i < end; i++) {
        int s = __ldg(&g_srcs[i]);
        const float* base = g_k + (size_t)s * 64 + lane * 2;
        float2 kk = *reinterpret_cast<const float2*>(base);
        float2 vv = *reinterpret_cast<const float2*>(g_v + (size_t)s * 64 + lane * 2);
        float p = qx * kk.x + qy * kk.y;
        #pragma unroll
        for (int o = 1; o < GROUP; o <<= 1) p += __shfl_xor_sync(0xffffffffu, p, o);
        float mn = fmaxf(m, p);
        float sc = __expf(m - mn);   // first iter: exp(-1e30 - p) = 0
        float w  = __expf(p - mn);
        den = den * sc + w;
        ax  = ax  * sc + w * vv.x;
        ay  = ay  * sc + w * vv.y;
        m = mn;
    }

    const float rden = (den > 0.f) ? (1.0f / den) : 0.0f;   // deg==0 -> out = skip
    float2 sk = *reinterpret_cast<const float2*>(skip + (size_t)warp * 64 + lane * 2);
    float ox = ax * rden + sk.x;
    float oy = ay * rden + sk.y;
    if (RELU) {
        ox = fmaxf(ox, 0.f);
        oy = fmaxf(oy, 0.f);
    }
    *reinterpret_cast<float2*>(out + (size_t)warp * 64 + lane * 2) = make_float2(ox, oy);
}

// ---------------- launch ------------------------------------------------------
extern "C" void kernel_launch(void* const* d_in, const int* in_sizes, int n_in,
                              void* d_out, int out_size) {
    (void)in_sizes; (void)n_in; (void)out_size;
    const float* x = (const float*)d_in[0];
    const int* ei = (const int*)d_in[1];

    // CSR by destination (shared by both layers)
    void* degp = nullptr;
    cudaGetSymbolAddress(&degp, g_deg);
    cudaMemsetAsync(degp, 0, NN * sizeof(int));
    hist_kernel<<<EE / 256, 256>>>(ei);
    scan_kernel<<<1, 1024>>>();
    scatter_kernel<<<EE / 256, 256>>>(ei);

    const dim3 ggrid((NN + 127) / 128, 4);

    // layer 1: H=4, D=16 -> qscale = 1/4
    G4w w1;
    w1.W[0] = (const float*)d_in[2];  w1.b[0] = (const float*)d_in[3];   // Wq1
    w1.W[1] = (const float*)d_in[4];  w1.b[1] = (const float*)d_in[5];   // Wk1
    w1.W[2] = (const float*)d_in[6];  w1.b[2] = (const float*)d_in[7];   // Wv1
    w1.W[3] = (const float*)d_in[8];  w1.b[3] = (const float*)d_in[9];   // Ws1
    gemm4_kernel<128, 1><<<ggrid, 128>>>(x, w1, 0.25f);
    node_attn_kernel<4, true, true><<<(NN * 32) / 256, 256>>>(nullptr);

    // layer 2: H=1, D=64 -> qscale = 1/8
    G4w w2;
    w2.W[0] = (const float*)d_in[10]; w2.b[0] = (const float*)d_in[11];  // Wq2
    w2.W[1] = (const float*)d_in[12]; w2.b[1] = (const float*)d_in[13];  // Wk2
    w2.W[2] = (const float*)d_in[14]; w2.b[2] = (const float*)d_in[15];  // Wv2
    w2.W[3] = (const float*)d_in[16]; w2.b[3] = (const float*)d_in[17];  // Ws2
    gemm4_kernel<64, 2><<<ggrid, 128>>>(x, w2, 0.125f);
    node_attn_kernel<1, false, false><<<(NN * 32) / 256, 256>>>((float*)d_out);
}

// round 3
// speedup vs baseline: 1.2257x; 1.0749x over previous
#include <cuda_runtime.h>
#include <cstdint>

#define NN 50000
#define EE 800000

// ---------------- scratch (device globals: no allocation allowed) ----------
__device__ float g_q[NN * 64];
__device__ float g_k[NN * 64];
__device__ float g_v[NN * 64];
__device__ float g_h[NN * 64];    // layer1 skip, then layer1 output (post-relu)
__device__ float g_s2[NN * 64];   // layer2 skip
__device__ int g_deg[NN];
__device__ int g_off[NN + 1];
__device__ int g_cur[NN];
__device__ int g_srcs[EE];

// ---------------- f32x2 helpers (sm_100+ packed fp32) -----------------------
__device__ __forceinline__ unsigned long long pack2(float x, float y) {
    unsigned long long r;
    asm("mov.b64 %0, {%1, %2};" : "=l"(r) : "f"(x), "f"(y));
    return r;
}
__device__ __forceinline__ float2 unpack2(unsigned long long v) {
    float2 r;
    asm("mov.b64 {%0, %1}, %2;" : "=f"(r.x), "=f"(r.y) : "l"(v));
    return r;
}
__device__ __forceinline__ unsigned long long ffma2(unsigned long long a,
                                                    unsigned long long b,
                                                    unsigned long long c) {
    unsigned long long d;
    asm("fma.rn.f32x2 %0, %1, %2, %3;" : "=l"(d) : "l"(a), "l"(b), "l"(c));
    return d;
}

// ---------------- CSR build --------------------------------------------------
__global__ void hist_kernel(const int* __restrict__ ei) {
    int e = blockIdx.x * blockDim.x + threadIdx.x;
    if (e < EE) atomicAdd(&g_deg[__ldg(ei + EE + e)], 1);
}

__global__ void scan_kernel() {
    __shared__ int sh[1024];
    const int tid = threadIdx.x;
    const int CHUNK = (NN + 1023) / 1024;   // 49
    const int s0 = tid * CHUNK;
    int sum = 0;
    #pragma unroll 4
    for (int i = 0; i < CHUNK; i++) {
        int idx = s0 + i;
        if (idx < NN) sum += g_deg[idx];
    }
    sh[tid] = sum;
    __syncthreads();
    int val = sum;
    for (int off = 1; off < 1024; off <<= 1) {
        int t = (tid >= off) ? sh[tid - off] : 0;
        __syncthreads();
        val += t;
        sh[tid] = val;
        __syncthreads();
    }
    int run = val - sum;   // exclusive prefix
    for (int i = 0; i < CHUNK; i++) {
        int idx = s0 + i;
        if (idx < NN) {
            g_off[idx] = run;
            g_cur[idx] = run;
            run += g_deg[idx];
        }
    }
    if (tid == 0) g_off[NN] = EE;
}

__global__ void scatter_kernel(const int* __restrict__ ei) {
    int e = blockIdx.x * blockDim.x + threadIdx.x;
    if (e < EE) {
        int d = __ldg(ei + EE + e);
        int p = atomicAdd(&g_cur[d], 1);
        g_srcs[p] = __ldg(ei + e);
    }
}

// ---------------- fused QKVS GEMM (double-buffered pipeline) -----------------
// O_m = (X @ W_m^T + b_m) * scale_m.  BM=128, BN=64 (full matrix), BK=32,
// 128 threads, 8x8 per thread, f32x2 accumulators.  Tile t+1 is LDG-prefetched
// into registers before computing tile t; stored to the alternate smem buffer
// after compute; one barrier per tile.
struct G4w {
    const float* W[4];
    const float* b[4];
};

template <int C, int LAYER>
__global__ __launch_bounds__(128) void gemm4_kernel(const float* __restrict__ Xin, G4w a,
                                                    float qscale) {
    __shared__ __align__(16) float Xs[2][32][132];
    __shared__ __align__(16) float Ws[2][32][68];
    constexpr int T = C / 32;

    const float* X = (LAYER == 1) ? Xin : g_h;
    const int mat = blockIdx.y;
    const float* W = a.W[mat];
    float* O = (mat == 0) ? g_q : (mat == 1) ? g_k : (mat == 2) ? g_v
               : ((LAYER == 1) ? g_h : g_s2);
    const float scale = (mat == 0) ? qscale : 1.0f;

    const int row0 = blockIdx.x * 128;
    const int tid = threadIdx.x;
    const int tx = tid & 7;    // 8 col group (TN=8)
    const int ty = tid >> 3;   // 16 row groups (TM=8)

    float4 xr[8];
    float4 wr[4];

    auto ldg_tile = [&](int t) {
        const int k0 = t * 32;
        #pragma unroll
        for (int u = 0; u < 8; u++) {
            int idx = tid + u * 128;
            int r = idx >> 3;
            int kq = idx & 7;
            int rg = row0 + r;
            xr[u] = (rg < NN)
                  ? *reinterpret_cast<const float4*>(X + (size_t)rg * C + k0 + kq * 4)
                  : make_float4(0.f, 0.f, 0.f, 0.f);
        }
        #pragma unroll
        for (int u = 0; u < 4; u++) {
            int idx = tid + u * 128;
            int m = idx >> 3;
            int kq = idx & 7;
            wr[u] = *reinterpret_cast<const float4*>(W + (size_t)m * C + k0 + kq * 4);
        }
    };
    auto store_tile = [&](int b) {
        #pragma unroll
        for (int u = 0; u < 8; u++) {
            int idx = tid + u * 128;
            int r = idx >> 3;
            int kq = idx & 7;
            Xs[b][kq * 4 + 0][r] = xr[u].x;
            Xs[b][kq * 4 + 1][r] = xr[u].y;
            Xs[b][kq * 4 + 2][r] = xr[u].z;
            Xs[b][kq * 4 + 3][r] = xr[u].w;
        }
        #pragma unroll
        for (int u = 0; u < 4; u++) {
            int idx = tid + u * 128;
            int m = idx >> 3;
            int kq = idx & 7;
            Ws[b][kq * 4 + 0][m] = wr[u].x;
            Ws[b][kq * 4 + 1][m] = wr[u].y;
            Ws[b][kq * 4 + 2][m] = wr[u].z;
            Ws[b][kq * 4 + 3][m] = wr[u].w;
        }
    };

    unsigned long long acc[8][4];
    #pragma unroll
    for (int i = 0; i < 8; i++)
        #pragma unroll
        for (int j = 0; j < 4; j++) acc[i][j] = 0ull;

    ldg_tile(0);
    store_tile(0);

    #pragma unroll
    for (int t = 0; t < T; t++) {
        __syncthreads();
        if (t + 1 < T) ldg_tile(t + 1);   // in flight during compute

        const int bsel = t & 1;
        #pragma unroll
        for (int k = 0; k < 32; k++) {
            float4 a0 = *reinterpret_cast<const float4*>(&Xs[bsel][k][ty * 8]);
            float4 a1 = *reinterpret_cast<const float4*>(&Xs[bsel][k][ty * 8 + 4]);
            const unsigned long long* bp =
                reinterpret_cast<const unsigned long long*>(&Ws[bsel][k][tx * 8]);
            unsigned long long b0 = bp[0], b1 = bp[1], b2 = bp[2], b3 = bp[3];
            float av[8] = {a0.x, a0.y, a0.z, a0.w, a1.x, a1.y, a1.z, a1.w};
            #pragma unroll
            for (int i = 0; i < 8; i++) {
                unsigned long long aa = pack2(av[i], av[i]);
                acc[i][0] = ffma2(aa, b0, acc[i][0]);
                acc[i][1] = ffma2(aa, b1, acc[i][1]);
                acc[i][2] = ffma2(aa, b2, acc[i][2]);
                acc[i][3] = ffma2(aa, b3, acc[i][3]);
            }
        }
        if (t + 1 < T) store_tile((t + 1) & 1);   // other buffer: safe pre-barrier
    }

    const float* bias = a.b[mat];
    float4 bv0 = *reinterpret_cast<const float4*>(bias + tx * 8);
    float4 bv1 = *reinterpret_cast<const float4*>(bias + tx * 8 + 4);
    #pragma unroll
    for (int i = 0; i < 8; i++) {
        int rg = row0 + ty * 8 + i;
        if (rg >= NN) continue;
        float2 c0 = unpack2(acc[i][0]);
        float2 c1 = unpack2(acc[i][1]);
        float2 c2 = unpack2(acc[i][2]);
        float2 c3 = unpack2(acc[i][3]);
        float4 o0 = make_float4((c0.x + bv0.x) * scale, (c0.y + bv0.y) * scale,
                                (c1.x + bv0.z) * scale, (c1.y + bv0.w) * scale);
        float4 o1 = make_float4((c2.x + bv1.x) * scale, (c2.y + bv1.y) * scale,
                                (c3.x + bv1.z) * scale, (c3.y + bv1.w) * scale);
        *reinterpret_cast<float4*>(O + (size_t)rg * 64 + tx * 8) = o0;
        *reinterpret_cast<float4*>(O + (size_t)rg * 64 + tx * 8 + 4) = o1;
    }
}

// ---------------- per-destination-node attention (warp per node) ------------
// Single-pass online softmax, edge loop unrolled x2 with batched gathers.
// q is pre-scaled by 1/sqrt(D) in the GEMM epilogue.
template <int H, bool RELU, bool L1>
__global__ void node_attn_kernel(float* __restrict__ out_param) {
    constexpr int GROUP = 32 / H;

    int warp = (blockIdx.x * blockDim.x + threadIdx.x) >> 5;
    if (warp >= NN) return;
    const int lane = threadIdx.x & 31;

    const float* skip = L1 ? g_h : g_s2;
    float* out = L1 ? g_h : out_param;

    const int beg = g_off[warp];
    const int end = g_off[warp + 1];

    float2 qr = *reinterpret_cast<const float2*>(g_q + (size_t)warp * 64 + lane * 2);
    const float qx = qr.x, qy = qr.y;

    float m = -1e30f;
    float den = 0.f, ax = 0.f, ay = 0.f;

    int i = beg;
    for (; i + 2 <= end; i += 2) {
        int s0 = __ldg(&g_srcs[i]);
        int s1 = __ldg(&g_srcs[i + 1]);
        float2 k0 = *reinterpret_cast<const float2*>(g_k + (size_t)s0 * 64 + lane * 2);
        float2 k1 = *reinterpret_cast<const float2*>(g_k + (size_t)s1 * 64 + lane * 2);
        float2 v0 = *reinterpret_cast<const float2*>(g_v + (size_t)s0 * 64 + lane * 2);
        float2 v1 = *reinterpret_cast<const float2*>(g_v + (size_t)s1 * 64 + lane * 2);
        float p0 = qx * k0.x + qy * k0.y;
        float p1 = qx * k1.x + qy * k1.y;
        #pragma unroll
        for (int o = 1; o < GROUP; o <<= 1) {
            p0 += __shfl_xor_sync(0xffffffffu, p0, o);
            p1 += __shfl_xor_sync(0xffffffffu, p1, o);
        }
        float mn = fmaxf(m, p0);
        float sc = __expf(m - mn);
        float w  = __expf(p0 - mn);
        den = den * sc + w;
        ax  = ax  * sc + w * v0.x;
        ay  = ay  * sc + w * v0.y;
        m = mn;

        mn = fmaxf(m, p1);
        sc = __expf(m - mn);
        w  = __expf(p1 - mn);
        den = den * sc + w;
        ax  = ax  * sc + w * v1.x;
        ay  = ay  * sc + w * v1.y;
        m = mn;
    }
    if (i < end) {
        int s = __ldg(&g_srcs[i]);
        float2 kk = *reinterpret_cast<const float2*>(g_k + (size_t)s * 64 + lane * 2);
        float2 vv = *reinterpret_cast<const float2*>(g_v + (size_t)s * 64 + lane * 2);
        float p = qx * kk.x + qy * kk.y;
        #pragma unroll
        for (int o = 1; o < GROUP; o <<= 1) p += __shfl_xor_sync(0xffffffffu, p, o);
        float mn = fmaxf(m, p);
        float sc = __expf(m - mn);
        float w  = __expf(p - mn);
        den = den * sc + w;
        ax  = ax  * sc + w * vv.x;
        ay  = ay  * sc + w * vv.y;
        m = mn;
    }

    const float rden = (den > 0.f) ? (1.0f / den) : 0.0f;   // deg==0 -> out = skip
    float2 sk = *reinterpret_cast<const float2*>(skip + (size_t)warp * 64 + lane * 2);
    float ox = ax * rden + sk.x;
    float oy = ay * rden + sk.y;
    if (RELU) {
        ox = fmaxf(ox, 0.f);
        oy = fmaxf(oy, 0.f);
    }
    *reinterpret_cast<float2*>(out + (size_t)warp * 64 + lane * 2) = make_float2(ox, oy);
}

// ---------------- launch ------------------------------------------------------
extern "C" void kernel_launch(void* const* d_in, const int* in_sizes, int n_in,
                              void* d_out, int out_size) {
    (void)in_sizes; (void)n_in; (void)out_size;
    const float* x = (const float*)d_in[0];
    const int* ei = (const int*)d_in[1];

    // CSR by destination (shared by both layers)
    void* degp = nullptr;
    cudaGetSymbolAddress(&degp, g_deg);
    cudaMemsetAsync(degp, 0, NN * sizeof(int));
    hist_kernel<<<EE / 256, 256>>>(ei);
    scan_kernel<<<1, 1024>>>();
    scatter_kernel<<<EE / 256, 256>>>(ei);

    const dim3 ggrid((NN + 127) / 128, 4);

    // layer 1: H=4, D=16 -> qscale = 1/4
    G4w w1;
    w1.W[0] = (const float*)d_in[2];  w1.b[0] = (const float*)d_in[3];   // Wq1
    w1.W[1] = (const float*)d_in[4];  w1.b[1] = (const float*)d_in[5];   // Wk1
    w1.W[2] = (const float*)d_in[6];  w1.b[2] = (const float*)d_in[7];   // Wv1
    w1.W[3] = (const float*)d_in[8];  w1.b[3] = (const float*)d_in[9];   // Ws1
    gemm4_kernel<128, 1><<<ggrid, 128>>>(x, w1, 0.25f);
    node_attn_kernel<4, true, true><<<(NN * 32) / 256, 256>>>(nullptr);

    // layer 2: H=1, D=64 -> qscale = 1/8
    G4w w2;
    w2.W[0] = (const float*)d_in[10]; w2.b[0] = (const float*)d_in[11];  // Wq2
    w2.W[1] = (const float*)d_in[12]; w2.b[1] = (const float*)d_in[13];  // Wk2
    w2.W[2] = (const float*)d_in[14]; w2.b[2] = (const float*)d_in[15];  // Wv2
    w2.W[3] = (const float*)d_in[16]; w2.b[3] = (const float*)d_in[17];  // Ws2
    gemm4_kernel<64, 2><<<ggrid, 128>>>(x, w2, 0.125f);
    node_attn_kernel<1, false, false><<<(NN * 32) / 256, 256>>>((float*)d_out);
}

// round 5
// speedup vs baseline: 1.4768x; 1.2049x over previous
#include <cuda_runtime.h>
#include <cuda_bf16.h>
#include <cstdint>

#define NN 50000
#define EE 800000

// ---------------- scratch (device globals: no allocation allowed) ----------
__device__ float g_q[NN * 64];
__device__ float g_k[NN * 64];
__device__ float g_v[NN * 64];
__device__ float g_h[NN * 64];    // layer1 skip, then layer1 output (post-relu)
__device__ float g_s2[NN * 64];   // layer2 skip
__device__ int g_deg[NN];
__device__ int g_off[NN + 1];
__device__ int g_cur[NN];
__device__ int g_srcs[EE];
// W in HMMA fragment layout: [mat][half(hi,lo)][kt][nt][lane] -> uint2
// layer1: KT=8 -> 4*2*8*8*32 = 16384 uint2; layer2: KT=4 -> 8192 uint2
__device__ __align__(16) uint2 g_w1[4 * 2 * 8 * 8 * 32];
__device__ __align__(16) uint2 g_w2[4 * 2 * 4 * 8 * 32];

struct G4w {
    const float* W[4];
    const float* b[4];
};

// ---------------- mma.sync m16n8k16 bf16 (sm_80+, portable PTX) -------------
__device__ __forceinline__ void mma_bf16(float* c, const uint32_t* a, const uint32_t* b) {
    asm volatile(
        "mma.sync.aligned.m16n8k16.row.col.f32.bf16.bf16.f32 "
        "{%0,%1,%2,%3}, {%4,%5,%6,%7}, {%8,%9}, {%0,%1,%2,%3};\n"
        : "+f"(c[0]), "+f"(c[1]), "+f"(c[2]), "+f"(c[3])
        : "r"(a[0]), "r"(a[1]), "r"(a[2]), "r"(a[3]), "r"(b[0]), "r"(b[1]));
}

__device__ __forceinline__ uint32_t pack_bf16x2(float x, float y) {
    __nv_bfloat162 h = __float22bfloat162_rn(make_float2(x, y));
    return *reinterpret_cast<uint32_t*>(&h);
}

// ---------------- CSR build --------------------------------------------------
__global__ void hist_kernel(const int* __restrict__ ei) {
    int e = blockIdx.x * blockDim.x + threadIdx.x;
    if (e < EE) atomicAdd(&g_deg[__ldg(ei + EE + e)], 1);
}

__global__ void scan_kernel() {
    __shared__ int sh[1024];
    const int tid = threadIdx.x;
    const int CHUNK = (NN + 1023) / 1024;
    const int s0 = tid * CHUNK;
    int sum = 0;
    #pragma unroll 4
    for (int i = 0; i < CHUNK; i++) {
        int idx = s0 + i;
        if (idx < NN) sum += g_deg[idx];
    }
    sh[tid] = sum;
    __syncthreads();
    int val = sum;
    for (int off = 1; off < 1024; off <<= 1) {
        int t = (tid >= off) ? sh[tid - off] : 0;
        __syncthreads();
        val += t;
        sh[tid] = val;
        __syncthreads();
    }
    int run = val - sum;
    for (int i = 0; i < CHUNK; i++) {
        int idx = s0 + i;
        if (idx < NN) {
            g_off[idx] = run;
            g_cur[idx] = run;
            run += g_deg[idx];
        }
    }
    if (tid == 0) g_off[NN] = EE;
}

__global__ void scatter_kernel(const int* __restrict__ ei) {
    int e = blockIdx.x * blockDim.x + threadIdx.x;
    if (e < EE) {
        int d = __ldg(ei + EE + e);
        int p = atomicAdd(&g_cur[d], 1);
        g_srcs[p] = __ldg(ei + e);
    }
}

// ---------------- W -> bf16 hi/lo HMMA-fragment conversion -------------------
// B fragment of m16n8k16 (row.col): per lane, reg0 = {B[k0][n], B[k0+1][n]},
// reg1 = {B[k0+8][n], B[k0+9][n]} with k0 = kt*16 + (lane%4)*2, n = nt*8 + lane/4.
// W is [n][k] row-major (out_features x in_features) -> B[k][n] = W[n][k].
__global__ void wprep_kernel(G4w w1, G4w w2) {
    int idx = blockIdx.x * blockDim.x + threadIdx.x;
    const int L1N = 4 * 8 * 8 * 32;   // 8192  (mat, kt, nt, lane)
    const int L2N = 4 * 4 * 8 * 32;   // 4096
    const float* W;
    uint2* dst;
    int C, KT, rem;
    if (idx < L1N) {
        C = 128; KT = 8;
        int mat = idx / (8 * 8 * 32);
        rem = idx - mat * (8 * 8 * 32);
        W = w1.W[mat];
        dst = g_w1 + (size_t)(mat * 2) * KT * 8 * 32;
    } else if (idx < L1N + L2N) {
        C = 64; KT = 4;
        int j = idx - L1N;
        int mat = j / (4 * 8 * 32);
        rem = j - mat * (4 * 8 * 32);
        W = w2.W[mat];
        dst = g_w2 + (size_t)(mat * 2) * KT * 8 * 32;
    } else {
        return;
    }
    int kt = rem / (8 * 32);
    int r2 = rem - kt * (8 * 32);
    int nt = r2 >> 5;
    int lane = r2 & 31;
    int k0 = kt * 16 + (lane & 3) * 2;
    int n = nt * 8 + (lane >> 2);

    float a0 = W[n * C + k0],     a1 = W[n * C + k0 + 1];
    float a2 = W[n * C + k0 + 8], a3 = W[n * C + k0 + 9];

    uint32_t h0 = pack_bf16x2(a0, a1);
    uint32_t h1 = pack_bf16x2(a2, a3);
    __nv_bfloat162* hp0 = reinterpret_cast<__nv_bfloat162*>(&h0);
    __nv_bfloat162* hp1 = reinterpret_cast<__nv_bfloat162*>(&h1);
    uint32_t l0 = pack_bf16x2(a0 - __bfloat162float(hp0->x), a1 - __bfloat162float(hp0->y));
    uint32_t l1 = pack_bf16x2(a2 - __bfloat162float(hp1->x), a3 - __bfloat162float(hp1->y));

    int fo = (kt * 8 + nt) * 32 + lane;
    dst[fo] = make_uint2(h0, h1);                    // hi half
    dst[KT * 8 * 32 + fo] = make_uint2(l0, l1);      // lo half
}

// ---------------- HMMA bf16-split fused QKVS GEMM ----------------------------
// 256 threads / CTA, 128 rows, all 4 mats.  Warp w: mat = w>>1, rowhalf = w&1
// (64 rows = 4 m-tiles).  A fragments staged in smem in fragment order
// (conflict-free LDS.128); B fragments straight from gmem (L1-hot LDG.64).
template <int C, int LAYER>
__global__ __launch_bounds__(256, 1) void gemm_mma_kernel(const float* __restrict__ Xin,
                                                          G4w a, float qscale) {
    constexpr int KT = C / 16;
    constexpr int HALF = KT * 8 * 32 * 4;     // b32 units per half
    extern __shared__ uint32_t sA[];          // [2][KT][8 mt][32 lane][4 regs]

    const float* X = (LAYER == 1) ? Xin : g_h;
    const int tid = threadIdx.x;
    const int row0 = blockIdx.x * 128;

    // ---- fill A fragments (hi/lo) ----
    constexpr int PAIRS = C / 2;
    for (int p = tid; p < 128 * PAIRS; p += 256) {
        int r = p / PAIRS;
        int kp = p - r * PAIRS;
        int rg = row0 + r;
        float2 xv = make_float2(0.f, 0.f);
        if (rg < NN) xv = *reinterpret_cast<const float2*>(X + (size_t)rg * C + kp * 2);
        uint32_t h = pack_bf16x2(xv.x, xv.y);
        __nv_bfloat162* hp = reinterpret_cast<__nv_bfloat162*>(&h);
        uint32_t l = pack_bf16x2(xv.x - __bfloat162float(hp->x),
                                 xv.y - __bfloat162float(hp->y));
        int m = r & 15, mt = r >> 4;
        int k = kp * 2, kt = k >> 4, kk = k & 15;
        int lane = (m & 7) * 4 + ((kk & 7) >> 1);
        int reg = ((m >> 3) & 1) | ((kk >> 3) << 1);
        int base = ((kt * 8 + mt) * 32 + lane) * 4 + reg;
        sA[base] = h;
        sA[HALF + base] = l;
    }
    __syncthreads();

    const int w = tid >> 5;
    const int lane = tid & 31;
    const int mat = w >> 1;
    const int rowhalf = w & 1;
    const uint2* Bh = ((LAYER == 1) ? g_w1 : g_w2) + (size_t)(mat * 2) * KT * 8 * 32;
    const uint2* Bl = Bh + KT * 8 * 32;

    float acc[4][8][4];
    #pragma unroll
    for (int i = 0; i < 4; i++)
        #pragma unroll
        for (int j = 0; j < 8; j++)
            #pragma unroll
            for (int q = 0; q < 4; q++) acc[i][j][q] = 0.f;

    #pragma unroll
    for (int kt = 0; kt < KT; kt++) {
        uint4 Ah[4], Al[4];
        #pragma unroll
        for (int mt4 = 0; mt4 < 4; mt4++) {
            int mt = rowhalf * 4 + mt4;
            int o = ((kt * 8 + mt) * 32 + lane) * 4;
            Ah[mt4] = *reinterpret_cast<const uint4*>(sA + o);
            Al[mt4] = *reinterpret_cast<const uint4*>(sA + HALF + o);
        }
        #pragma unroll
        for (int nt = 0; nt < 8; nt++) {
            uint2 bh = __ldg(Bh + (kt * 8 + nt) * 32 + lane);
            uint2 bl = __ldg(Bl + (kt * 8 + nt) * 32 + lane);
            #pragma unroll
            for (int mt4 = 0; mt4 < 4; mt4++) {
                mma_bf16(acc[mt4][nt], reinterpret_cast<uint32_t*>(&Ah[mt4]),
                         reinterpret_cast<uint32_t*>(&bh));
                mma_bf16(acc[mt4][nt], reinterpret_cast<uint32_t*>(&Ah[mt4]),
                         reinterpret_cast<uint32_t*>(&bl));
                mma_bf16(acc[mt4][nt], reinterpret_cast<uint32_t*>(&Al[mt4]),
                         reinterpret_cast<uint32_t*>(&bh));
            }
        }
    }

    // ---- epilogue: bias + scale + fp32 store ----
    float* O = (mat == 0) ? g_q : (mat == 1) ? g_k : (mat == 2) ? g_v
               : ((LAYER == 1) ? g_h : g_s2);
    const float sc = (mat == 0) ? qscale : 1.0f;
    const float* bias = a.b[mat];
    #pragma unroll
    for (int nt = 0; nt < 8; nt++) {
        int col = nt * 8 + (lane & 3) * 2;
        float b0 = __ldg(bias + col);
        float b1 = __ldg(bias + col + 1);
        #pragma unroll
        for (int mt4 = 0; mt4 < 4; mt4++) {
            int r = row0 + rowhalf * 64 + mt4 * 16 + (lane >> 2);
            if (r < NN)
                *reinterpret_cast<float2*>(O + (size_t)r * 64 + col) =
                    make_float2((acc[mt4][nt][0] + b0) * sc, (acc[mt4][nt][1] + b1) * sc);
            int r2 = r + 8;
            if (r2 < NN)
                *reinterpret_cast<float2*>(O + (size_t)r2 * 64 + col) =
                    make_float2((acc[mt4][nt][2] + b0) * sc, (acc[mt4][nt][3] + b1) * sc);
        }
    }
}

// ---------------- per-destination-node attention (warp per node) ------------
template <int H, bool RELU, bool L1>
__global__ void node_attn_kernel(float* __restrict__ out_param) {
    constexpr int GROUP = 32 / H;

    int warp = (blockIdx.x * blockDim.x + threadIdx.x) >> 5;
    if (warp >= NN) return;
    const int lane = threadIdx.x & 31;

    const float* skip = L1 ? g_h : g_s2;
    float* out = L1 ? g_h : out_param;

    const int beg = g_off[warp];
    const int end = g_off[warp + 1];

    float2 qr = *reinterpret_cast<const float2*>(g_q + (size_t)warp * 64 + lane * 2);
    const float qx = qr.x, qy = qr.y;

    float m = -1e30f;
    float den = 0.f, ax = 0.f, ay = 0.f;

    int i = beg;
    for (; i + 2 <= end; i += 2) {
        int s0 = __ldg(&g_srcs[i]);
        int s1 = __ldg(&g_srcs[i + 1]);
        float2 k0 = *reinterpret_cast<const float2*>(g_k + (size_t)s0 * 64 + lane * 2);
        float2 k1 = *reinterpret_cast<const float2*>(g_k + (size_t)s1 * 64 + lane * 2);
        float2 v0 = *reinterpret_cast<const float2*>(g_v + (size_t)s0 * 64 + lane * 2);
        float2 v1 = *reinterpret_cast<const float2*>(g_v + (size_t)s1 * 64 + lane * 2);
        float p0 = qx * k0.x + qy * k0.y;
        float p1 = qx * k1.x + qy * k1.y;
        #pragma unroll
        for (int o = 1; o < GROUP; o <<= 1) {
            p0 += __shfl_xor_sync(0xffffffffu, p0, o);
            p1 += __shfl_xor_sync(0xffffffffu, p1, o);
        }
        float mn = fmaxf(m, p0);
        float sc = __expf(m - mn);
        float w  = __expf(p0 - mn);
        den = den * sc + w;
        ax  = ax  * sc + w * v0.x;
        ay  = ay  * sc + w * v0.y;
        m = mn;

        mn = fmaxf(m, p1);
        sc = __expf(m - mn);
        w  = __expf(p1 - mn);
        den = den * sc + w;
        ax  = ax  * sc + w * v1.x;
        ay  = ay  * sc + w * v1.y;
        m = mn;
    }
    if (i < end) {
        int s = __ldg(&g_srcs[i]);
        float2 kk = *reinterpret_cast<const float2*>(g_k + (size_t)s * 64 + lane * 2);
        float2 vv = *reinterpret_cast<const float2*>(g_v + (size_t)s * 64 + lane * 2);
        float p = qx * kk.x + qy * kk.y;
        #pragma unroll
        for (int o = 1; o < GROUP; o <<= 1) p += __shfl_xor_sync(0xffffffffu, p, o);
        float mn = fmaxf(m, p);
        float sc = __expf(m - mn);
        float w  = __expf(p - mn);
        den = den * sc + w;
        ax  = ax  * sc + w * vv.x;
        ay  = ay  * sc + w * vv.y;
        m = mn;
    }

    const float rden = (den > 0.f) ? (1.0f / den) : 0.0f;   // deg==0 -> out = skip
    float2 sk = *reinterpret_cast<const float2*>(skip + (size_t)warp * 64 + lane * 2);
    float ox = ax * rden + sk.x;
    float oy = ay * rden + sk.y;
    if (RELU) {
        ox = fmaxf(ox, 0.f);
        oy = fmaxf(oy, 0.f);
    }
    *reinterpret_cast<float2*>(out + (size_t)warp * 64 + lane * 2) = make_float2(ox, oy);
}

// ---------------- launch ------------------------------------------------------
extern "C" void kernel_launch(void* const* d_in, const int* in_sizes, int n_in,
                              void* d_out, int out_size) {
    (void)in_sizes; (void)n_in; (void)out_size;
    const float* x = (const float*)d_in[0];
    const int* ei = (const int*)d_in[1];

    constexpr int SMEM1 = 2 * 8 * 8 * 32 * 16;   // 65536 bytes (C=128)
    constexpr int SMEM2 = 2 * 4 * 8 * 32 * 16;   // 32768 bytes (C=64)
    cudaFuncSetAttribute(gemm_mma_kernel<128, 1>,
                         cudaFuncAttributeMaxDynamicSharedMemorySize, SMEM1);
    cudaFuncSetAttribute(gemm_mma_kernel<64, 2>,
                         cudaFuncAttributeMaxDynamicSharedMemorySize, SMEM2);

    // CSR by destination (shared by both layers)
    void* degp = nullptr;
    cudaGetSymbolAddress(&degp, g_deg);
    cudaMemsetAsync(degp, 0, NN * sizeof(int));
    hist_kernel<<<EE / 256, 256>>>(ei);
    scan_kernel<<<1, 1024>>>();
    scatter_kernel<<<EE / 256, 256>>>(ei);

    G4w w1, w2;
    w1.W[0] = (const float*)d_in[2];  w1.b[0] = (const float*)d_in[3];
    w1.W[1] = (const float*)d_in[4];  w1.b[1] = (const float*)d_in[5];
    w1.W[2] = (const float*)d_in[6];  w1.b[2] = (const float*)d_in[7];
    w1.W[3] = (const float*)d_in[8];  w1.b[3] = (const float*)d_in[9];
    w2.W[0] = (const float*)d_in[10]; w2.b[0] = (const float*)d_in[11];
    w2.W[1] = (const float*)d_in[12]; w2.b[1] = (const float*)d_in[13];
    w2.W[2] = (const float*)d_in[14]; w2.b[2] = (const float*)d_in[15];
    w2.W[3] = (const float*)d_in[16]; w2.b[3] = (const float*)d_in[17];

    wprep_kernel<<<48, 256>>>(w1, w2);

    const int NB = (NN + 127) / 128;   // 391

    // layer 1: H=4, D=16 -> qscale = 1/4
    gemm_mma_kernel<128, 1><<<NB, 256, SMEM1>>>(x, w1, 0.25f);
    node_attn_kernel<4, true, true><<<(NN * 32) / 256, 256>>>(nullptr);

    // layer 2: H=1, D=64 -> qscale = 1/8
    gemm_mma_kernel<64, 2><<<NB, 256, SMEM2>>>(x, w2, 0.125f);
    node_attn_kernel<1, false, false><<<(NN * 32) / 256, 256>>>((float*)d_out);
}